// round 13
// baseline (speedup 1.0000x reference)
#include <cuda_runtime.h>
#include <cstdint>

#define BATCH  16
#define TLEN   4096
#define DIM    512
#define CHUNK  32
#define MEMSZ  64
#define NSPLIT 8
#define DSLICE (DIM / NSPLIT)     // 64
#define NSTEP  (TLEN / CHUNK)     // 128
#define NBLK   (BATCH * NSPLIT)   // 128 blocks, all co-resident
#define NTHR   256
#define EPSF   1e-10f
#define CP     (CHUNK + 4)        // chunkS pitch 36 (16B-aligned rows)
#define MP     (MEMSZ + 4)        // memS pitch 68 (16B-aligned rows)

// ---- cross-block scratch (parity double-buffered) ----
__device__ float    g_plog[2][BATCH][NSPLIT][CHUNK][MEMSZ];
__device__ float    g_pdot[2][BATCH][NSPLIT][MEMSZ];
__device__ float    g_pmm [2][BATCH][NSPLIT][MEMSZ];
__device__ float    g_pnn [2][BATCH][NSPLIT];
__device__ float    g_ent [NSTEP][BATCH];    // entropy: payload == ready flag (never 0.0)
__device__ unsigned g_cnt [NSTEP][BATCH];    // per-(step,batch) arrival counter

__global__ void zero_flags_kernel() {
    int t = blockIdx.x * blockDim.x + threadIdx.x;
    if (t < NSTEP * BATCH) {
        ((float*)g_ent)[t]    = 0.0f;
        ((unsigned*)g_cnt)[t] = 0u;
    }
}

#define BAR1() asm volatile("bar.sync 1, 128;" ::: "memory")
#define BAR2() asm volatile("bar.sync 2, 128;" ::: "memory")

// full partial-logits tile for this d-slice (128 threads, t = 0..127)
// each output keeps the exact d=0..63 fmaf chain (bit-identical to R11)
__device__ __forceinline__ void pre_gemm(const float (*cS)[CP], const float (*mS)[MP],
                                         float* plog, int t) {
    const int ic = t >> 4;   // c base 4*ic
    const int jm = t & 15;   // m base 4*jm
    float a[4][4];
    #pragma unroll
    for (int r = 0; r < 4; ++r)
        #pragma unroll
        for (int q = 0; q < 4; ++q) a[r][q] = 0.0f;
    #pragma unroll 4
    for (int d = 0; d < DSLICE; ++d) {
        float4 cv = *(const float4*)&cS[d][4 * ic];
        float4 mv = *(const float4*)&mS[d][4 * jm];
        float cc[4] = {cv.x, cv.y, cv.z, cv.w};
        float mm[4] = {mv.x, mv.y, mv.z, mv.w};
        #pragma unroll
        for (int r = 0; r < 4; ++r)
            #pragma unroll
            for (int q = 0; q < 4; ++q)
                a[r][q] = fmaf(cc[r], mm[q], a[r][q]);
    }
    #pragma unroll
    for (int r = 0; r < 4; ++r)
        __stcg((float4*)(plog + (size_t)(4 * ic + r) * MEMSZ + 4 * jm),
               make_float4(a[r][0], a[r][1], a[r][2], a[r][3]));
}

// newm for this d-slice: exact serial c-chain
__device__ __forceinline__ void pre_newm(const float (*cS)[CP], float* nm, int t) {
    if (t < DSLICE) {
        float mx = cS[t][0];
        #pragma unroll
        for (int c = 1; c < CHUNK; ++c) mx = fmaxf(mx, cS[t][c]);
        nm[t] = mx;
    }
}

// sim partials (needs nm complete -> call after BAR2)
__device__ __forceinline__ void pre_sim(const float (*mS)[MP], const float* nm,
                                        float* pdot, float* pmm, float* pnn, int t) {
    if (t < MEMSZ) {
        float pd = 0.0f, pm = 0.0f;
        #pragma unroll 4
        for (int d = 0; d < DSLICE; ++d) {
            float mv = mS[d][t];
            pd = fmaf(nm[d], mv, pd);
            pm = fmaf(mv, mv, pm);
        }
        __stcg(pdot + t, pd);
        __stcg(pmm + t, pm);
    } else if (t < MEMSZ + 32) {
        int l = t - MEMSZ;
        float n0 = nm[l], n1 = nm[l + 32];
        float nn = n0 * n0 + n1 * n1;
        #pragma unroll
        for (int o = 16; o; o >>= 1) nn += __shfl_xor_sync(0xffffffffu, nn, o);
        if (l == 0) __stcg(pnn, nn);
    }
}

__global__ void __launch_bounds__(NTHR, 1)
memk(const float* __restrict__ x, const float* __restrict__ mem_init,
     float* __restrict__ out)
{
    __shared__ float memS  [DSLICE][MP];   // [d][m]
    __shared__ float chunkS[DSLICE][CP];   // [d][c]
    __shared__ float logS  [CHUNK][MEMSZ];
    __shared__ float newmB [2][DSLICE];    // newm parity buffers
    __shared__ float score [MEMSZ];
    __shared__ float msS   [MEMSZ];
    __shared__ float mfS   [MEMSZ];
    __shared__ float simS  [MEMSZ];
    __shared__ float entS  [BATCH];
    __shared__ int   sRepl, sMerge, sChange;

    const int tid  = threadIdx.x;
    const int bid  = blockIdx.x;
    const int b    = bid / NSPLIT;
    const int s    = bid % NSPLIT;
    const int d0   = s * DSLICE;
    const int lane = tid & 31;
    const int warp = tid >> 5;

    // init mem slice: mem_init[b][m][d0+d] -> memS[d][m]
    for (int i = tid; i < DSLICE * MEMSZ; i += NTHR) {
        int m = i >> 6;
        int d = i & 63;
        memS[d][m] = mem_init[((size_t)b * MEMSZ + m) * DIM + d0 + d];
    }
    for (int i = tid; i < MEMSZ; i += NTHR) { msS[i] = 0.0f; mfS[i] = 0.0f; }

    const float scale = 1.0f / sqrtf((float)DIM);
    const float thr   = 0.5f * log2f((float)MEMSZ + EPSF);  // = 3.0

    // chunk-load decomposition: thread owns q0 = tid and q1 = tid + 256
    const int q0_c = tid >> 4,         q0_d = tid & 15;
    const int q1_c = (tid + 256) >> 4, q1_d = tid & 15;

    // prologue: fetch chunk 0 into registers, install, then pre-work for step 0
    float4 v0, v1;
    {
        const float* xb = x + ((size_t)b * TLEN) * DIM + d0;
        v0 = *(const float4*)(xb + (size_t)q0_c * DIM + q0_d * 4);
        v1 = *(const float4*)(xb + (size_t)q1_c * DIM + q1_d * 4);
    }
    chunkS[q0_d * 4 + 0][q0_c] = v0.x; chunkS[q0_d * 4 + 1][q0_c] = v0.y;
    chunkS[q0_d * 4 + 2][q0_c] = v0.z; chunkS[q0_d * 4 + 3][q0_c] = v0.w;
    chunkS[q1_d * 4 + 0][q1_c] = v1.x; chunkS[q1_d * 4 + 1][q1_c] = v1.y;
    chunkS[q1_d * 4 + 2][q1_c] = v1.z; chunkS[q1_d * 4 + 3][q1_c] = v1.w;
    __syncthreads();   // memS + chunk0 ready

    // prefetch chunk 1 (regs freed by install above)
    {
        const float* xb = x + ((size_t)b * TLEN + (size_t)CHUNK) * DIM + d0;
        v0 = *(const float4*)(xb + (size_t)q0_c * DIM + q0_d * 4);
        v1 = *(const float4*)(xb + (size_t)q1_c * DIM + q1_d * 4);
    }
    // step-0 partials (buffer 0), warps 4-7
    if (tid >= 128) {
        int t = tid - 128;
        pre_gemm(chunkS, memS, &g_plog[0][b][s][0][0], t);
        pre_newm(chunkS, newmB[0], t);
        BAR2();
        pre_sim(memS, newmB[0], &g_pdot[0][b][s][0], &g_pmm[0][b][s][0],
                &g_pnn[0][b][s], t);
    }

    for (int step = 0; step < NSTEP; ++step) {
        const int p = step & 1;

        // ===== P1: fixup changed column m* (partials otherwise precomputed) ====
        if (step > 0) {
            int mstar = sChange;
            if (tid < CHUNK) {
                float acc = 0.0f;
                #pragma unroll 4
                for (int d = 0; d < DSLICE; ++d)
                    acc = fmaf(chunkS[d][tid], memS[d][mstar], acc);
                __stcg(&g_plog[p][b][s][tid][mstar], acc);
            } else if (tid == CHUNK) {
                float pd = 0.0f, pm = 0.0f;
                #pragma unroll 4
                for (int d = 0; d < DSLICE; ++d) {
                    float mv = memS[d][mstar];
                    pd = fmaf(newmB[p][d], mv, pd);
                    pm = fmaf(mv, mv, pm);
                }
                __stcg(&g_pdot[p][b][s][mstar], pd);
                __stcg(&g_pmm [p][b][s][mstar], pm);
            }
        }

        // per-batch barrier (proven scheme): release, arrive, spin for 8 siblings
        __threadfence();
        __syncthreads();
        if (tid == 0) {
            atomicAdd(&g_cnt[step][b], 1u);
            const volatile unsigned* pc = &g_cnt[step][b];
            while (*pc < (unsigned)NSPLIT) { }
            __threadfence();
        }
        __syncthreads();

        // install chunk s+1 (regs -> SMEM); chunk s no longer needed
        if (step + 1 < NSTEP) {
            chunkS[q0_d * 4 + 0][q0_c] = v0.x; chunkS[q0_d * 4 + 1][q0_c] = v0.y;
            chunkS[q0_d * 4 + 2][q0_c] = v0.z; chunkS[q0_d * 4 + 3][q0_c] = v0.w;
            chunkS[q1_d * 4 + 0][q1_c] = v1.x; chunkS[q1_d * 4 + 1][q1_c] = v1.y;
            chunkS[q1_d * 4 + 2][q1_c] = v1.z; chunkS[q1_d * 4 + 3][q1_c] = v1.w;
        }
        __syncthreads();
        // prefetch chunk s+2
        if (step + 2 < NSTEP) {
            const float* xb = x + ((size_t)b * TLEN + (size_t)(step + 2) * CHUNK) * DIM + d0;
            v0 = *(const float4*)(xb + (size_t)q0_c * DIM + q0_d * 4);
            v1 = *(const float4*)(xb + (size_t)q1_c * DIM + q1_d * 4);
        }

        // ===== split: warps 0-3 consumer chain | warps 4-7 next-step pre-work ==
        if (tid < 128) {
            // -- reduce partial logits (exact ss=0..7 split order) --
            for (int q = tid; q < CHUNK * (MEMSZ / 4); q += 128) {
                int c  = q >> 4;
                int mq = q & 15;
                float4 r = make_float4(0, 0, 0, 0);
                #pragma unroll
                for (int ss = 0; ss < NSPLIT; ++ss) {
                    float4 t4 = __ldcg((const float4*)&g_plog[p][b][ss][c][mq * 4]);
                    r.x += t4.x; r.y += t4.y; r.z += t4.z; r.w += t4.w;
                }
                *(float4*)&logS[c][4 * mq] = r;
            }
            BAR1();
            // -- softmax rows (4 warps, 8 rows each) --
            for (int c = warp; c < CHUNK; c += 4) {
                float w0 = logS[c][lane]      * scale;
                float w1 = logS[c][lane + 32] * scale;
                float mx = fmaxf(w0, w1);
                #pragma unroll
                for (int o = 16; o; o >>= 1) mx = fmaxf(mx, __shfl_xor_sync(0xffffffffu, mx, o));
                float e0 = __expf(w0 - mx), e1 = __expf(w1 - mx);
                float sm = e0 + e1;
                #pragma unroll
                for (int o = 16; o; o >>= 1) sm += __shfl_xor_sync(0xffffffffu, sm, o);
                float inv = 1.0f / sm;
                logS[c][lane]      = e0 * inv;
                logS[c][lane + 32] = e1 * inv;
            }
            BAR1();
            // -- score (exact serial c=0..31) | sim reduce (exact ss order) --
            if (tid < MEMSZ) {
                float sc = 0.0f;
                #pragma unroll
                for (int c = 0; c < CHUNK; ++c) sc += logS[c][tid];
                score[tid] = sc * (1.0f / CHUNK);
            } else {
                int m = tid - MEMSZ;
                float pd = 0.0f, pm = 0.0f, nn = 0.0f;
                #pragma unroll
                for (int ss = 0; ss < NSPLIT; ++ss) {
                    pd += __ldcg(&g_pdot[p][b][ss][m]);
                    pm += __ldcg(&g_pmm [p][b][ss][m]);
                    nn += __ldcg(&g_pnn [p][b][ss]);
                }
                simS[m] = pd / (sqrtf(nn + 1e-8f) * sqrtf(pm + 1e-8f));
            }
            BAR1();
            if (warp == 0) {
                float s0 = score[lane], s1 = score[lane + 32];
                float e = -(log2f(s0 + EPSF) * s0 + log2f(s1 + EPSF) * s1);
                #pragma unroll
                for (int o = 16; o; o >>= 1) e += __shfl_xor_sync(0xffffffffu, e, o);
                if (lane == 0 && s == 0) __stcg(&g_ent[step][b], e);
            } else if (warp == 1) {
                float r0 = (msS[lane]      + score[lane])      / (mfS[lane]      + 1.0f);
                float r1 = (msS[lane + 32] + score[lane + 32]) / (mfS[lane + 32] + 1.0f);
                float v; int idx;
                if (r1 < r0) { v = r1; idx = lane + 32; } else { v = r0; idx = lane; }
                #pragma unroll
                for (int o = 16; o; o >>= 1) {
                    float ov = __shfl_xor_sync(0xffffffffu, v, o);
                    int   oi = __shfl_xor_sync(0xffffffffu, idx, o);
                    if (ov < v || (ov == v && oi < idx)) { v = ov; idx = oi; }
                }
                if (lane == 0) sRepl = idx;
            } else if (warp == 2) {
                float w0 = simS[lane], w1 = simS[lane + 32];
                float v; int idx;
                if (w1 > w0) { v = w1; idx = lane + 32; } else { v = w0; idx = lane; }
                #pragma unroll
                for (int o = 16; o; o >>= 1) {
                    float ov = __shfl_xor_sync(0xffffffffu, v, o);
                    int   oi = __shfl_xor_sync(0xffffffffu, idx, o);
                    if (ov > v || (ov == v && oi < idx)) { v = ov; idx = oi; }
                }
                if (lane == 0) sMerge = idx;
            } else if (warp == 3 && lane < BATCH) {
                // cross-batch entropy: payload-as-flag spin on per-step slots
                const volatile float* pe = &g_ent[step][lane];
                float v;
                do { v = *pe; } while (v == 0.0f);
                entS[lane] = v;
            }
        } else if (step + 1 < NSTEP) {
            // pre-work for step s+1 against mem_s (changed column fixed next P1)
            int t  = tid - 128;
            int pn = p ^ 1;
            pre_gemm(chunkS, memS, &g_plog[pn][b][s][0][0], t);
            pre_newm(chunkS, newmB[pn], t);
            BAR2();
            pre_sim(memS, newmB[pn], &g_pdot[pn][b][s][0], &g_pmm[pn][b][s][0],
                    &g_pnn[pn][b][s], t);
        }
        __syncthreads();

        // ===== P3: global branch + slice-local update ==========================
        float em = 0.0f;
        #pragma unroll
        for (int bb = 0; bb < BATCH; ++bb) em += entS[bb];   // exact serial order
        em *= (1.0f / BATCH);

        if (em > thr) {
            int rm = sRepl;
            if (tid < DSLICE) {
                memS[tid][rm] = newmB[p][tid];
            } else if (tid < DSLICE + MEMSZ) {
                int m = tid - DSLICE;
                float sn = msS[m] + score[m];
                float fn = mfS[m] + 1.0f;
                if (m == rm) { sn = 0.0f; fn = 1.0f; }
                msS[m] = sn; mfS[m] = fn;
            }
        } else {
            int im = sMerge;
            if (tid < DSLICE) {
                float old = memS[tid][im];
                memS[tid][im] = old + (0.7f * newmB[p][tid] - 0.7f * old);
            }
        }
        if (tid == 0) sChange = (em > thr) ? sRepl : sMerge;
        __syncthreads();
    }

    // write final mem slice
    for (int i = tid; i < MEMSZ * DSLICE; i += NTHR) {
        int m = i >> 6;
        int d = i & 63;
        out[((size_t)b * MEMSZ + m) * DIM + d0 + d] = memS[d][m];
    }
}

extern "C" void kernel_launch(void* const* d_in, const int* in_sizes, int n_in,
                              void* d_out, int out_size) {
    const float* x        = (const float*)d_in[0];
    const float* mem_init = (const float*)d_in[1];
    if (n_in >= 2 && in_sizes[0] < in_sizes[1]) {
        const float* t = x; x = mem_init; mem_init = t;
    }
    float* out = (float*)d_out;

    zero_flags_kernel<<<4, 512>>>();
    memk<<<NBLK, NTHR>>>(x, mem_init, out);
}

// round 14
// speedup vs baseline: 1.1482x; 1.1482x over previous
#include <cuda_runtime.h>
#include <cstdint>

#define BATCH  16
#define TLEN   4096
#define DIM    512
#define CHUNK  32
#define MEMSZ  64
#define NSPLIT 8
#define DSLICE (DIM / NSPLIT)     // 64
#define NSTEP  (TLEN / CHUNK)     // 128
#define NBLK   (BATCH * NSPLIT)   // 128 blocks, all co-resident
#define NTHR   256
#define EPSF   1e-10f

// ---- cross-block scratch (parity double-buffered) ----
__device__ float    g_plog[2][BATCH][NSPLIT][CHUNK][MEMSZ];
__device__ float    g_pdot[2][BATCH][NSPLIT][MEMSZ];
__device__ float    g_pmm [2][BATCH][NSPLIT][MEMSZ];
__device__ float    g_pnn [2][BATCH][NSPLIT];
__device__ float    g_ent [NSTEP][BATCH];    // entropy: payload == ready flag (never 0.0)
__device__ unsigned g_cnt [NSTEP][BATCH];    // per-(step,batch) arrival counter

__global__ void zero_flags_kernel() {
    int t = blockIdx.x * blockDim.x + threadIdx.x;
    if (t < NSTEP * BATCH) {
        ((float*)g_ent)[t]    = 0.0f;
        ((unsigned*)g_cnt)[t] = 0u;
    }
}

__global__ void __launch_bounds__(NTHR, 1)
memk(const float* __restrict__ x, const float* __restrict__ mem_init,
     float* __restrict__ out)
{
    __shared__ float memS  [DSLICE][MEMSZ + 4]; // [d][m], pitch 68
    __shared__ float chunkS[DSLICE][CHUNK + 2]; // [d][c], pitch 34 (float2-safe)
    __shared__ float logS  [CHUNK][MEMSZ];
    __shared__ float newmB [2][DSLICE];         // newm parity buffers
    __shared__ float score [MEMSZ];
    __shared__ float msS   [MEMSZ];
    __shared__ float mfS   [MEMSZ];
    __shared__ float simS  [MEMSZ];
    __shared__ float entS  [BATCH];
    __shared__ int   sRepl, sMerge, sChange;

    const int tid  = threadIdx.x;
    const int bid  = blockIdx.x;
    const int b    = bid / NSPLIT;
    const int s    = bid % NSPLIT;
    const int d0   = s * DSLICE;
    const int lane = tid & 31;
    const int warp = tid >> 5;

    // init mem slice: mem_init[b][m][d0+d] -> memS[d][m]
    for (int i = tid; i < DSLICE * MEMSZ; i += NTHR) {
        int m = i >> 6;
        int d = i & 63;
        memS[d][m] = mem_init[((size_t)b * MEMSZ + m) * DIM + d0 + d];
    }
    for (int i = tid; i < MEMSZ; i += NTHR) { msS[i] = 0.0f; mfS[i] = 0.0f; }

    const float scale = 1.0f / sqrtf((float)DIM);
    const float thr   = 0.5f * log2f((float)MEMSZ + EPSF);  // = 3.0

    // GEMM 2c x 4m tile on all 256 threads (R9-proven layout)
    const int i_c = tid >> 4;   // c pair base 2*i_c
    const int j_m = tid & 15;   // m quad base 4*j_m

    // chunk-load decomposition: thread owns q0 = tid and q1 = tid + 256
    const int q0_c = tid >> 4,         q0_d = tid & 15;
    const int q1_c = (tid + 256) >> 4, q1_d = tid & 15;

    // prologue: fetch chunk 0, install, then full pre-phase for step 0 (buffer 0)
    float4 v0, v1;
    {
        const float* xb = x + ((size_t)b * TLEN) * DIM + d0;
        v0 = *(const float4*)(xb + (size_t)q0_c * DIM + q0_d * 4);
        v1 = *(const float4*)(xb + (size_t)q1_c * DIM + q1_d * 4);
    }
    __syncthreads();   // memS init complete
    chunkS[q0_d * 4 + 0][q0_c] = v0.x; chunkS[q0_d * 4 + 1][q0_c] = v0.y;
    chunkS[q0_d * 4 + 2][q0_c] = v0.z; chunkS[q0_d * 4 + 3][q0_c] = v0.w;
    chunkS[q1_d * 4 + 0][q1_c] = v1.x; chunkS[q1_d * 4 + 1][q1_c] = v1.y;
    chunkS[q1_d * 4 + 2][q1_c] = v1.z; chunkS[q1_d * 4 + 3][q1_c] = v1.w;
    __syncthreads();
    // prefetch chunk 1
    {
        const float* xb = x + ((size_t)b * TLEN + (size_t)CHUNK) * DIM + d0;
        v0 = *(const float4*)(xb + (size_t)q0_c * DIM + q0_d * 4);
        v1 = *(const float4*)(xb + (size_t)q1_c * DIM + q1_d * 4);
    }

    // ---- pre-phase (R9 phase-1 verbatim) for a given parity buffer ----
    // (written as a macro-like lambda to keep code identical in both call sites)
    #define PRE_PHASE(PP)                                                        \
    do {                                                                         \
        float a00=0,a01=0,a02=0,a03=0, a10=0,a11=0,a12=0,a13=0;                  \
        _Pragma("unroll 4")                                                      \
        for (int d = 0; d < DSLICE; ++d) {                                       \
            float2 av = *(const float2*)&chunkS[d][2 * i_c];                     \
            float4 bv = *(const float4*)&memS[d][4 * j_m];                       \
            a00 = fmaf(av.x, bv.x, a00); a01 = fmaf(av.x, bv.y, a01);            \
            a02 = fmaf(av.x, bv.z, a02); a03 = fmaf(av.x, bv.w, a03);            \
            a10 = fmaf(av.y, bv.x, a10); a11 = fmaf(av.y, bv.y, a11);            \
            a12 = fmaf(av.y, bv.z, a12); a13 = fmaf(av.y, bv.w, a13);            \
        }                                                                        \
        __stcg((float4*)&g_plog[PP][b][s][2 * i_c][4 * j_m],                     \
               make_float4(a00, a01, a02, a03));                                 \
        __stcg((float4*)&g_plog[PP][b][s][2 * i_c + 1][4 * j_m],                 \
               make_float4(a10, a11, a12, a13));                                 \
        if (tid < DSLICE) {                                                      \
            float mx = chunkS[tid][0];                                           \
            _Pragma("unroll")                                                    \
            for (int c = 1; c < CHUNK; ++c) mx = fmaxf(mx, chunkS[tid][c]);      \
            newmB[PP][tid] = mx;                                                 \
        }                                                                        \
        __syncthreads();                                                         \
        if (tid < MEMSZ) {                                                       \
            float pd = 0.0f, pm = 0.0f;                                          \
            _Pragma("unroll 4")                                                  \
            for (int d = 0; d < DSLICE; ++d) {                                   \
                float mv = memS[d][tid];                                         \
                pd = fmaf(newmB[PP][d], mv, pd);                                 \
                pm = fmaf(mv, mv, pm);                                           \
            }                                                                    \
            __stcg(&g_pdot[PP][b][s][tid], pd);                                  \
            __stcg(&g_pmm [PP][b][s][tid], pm);                                  \
        } else if (tid < MEMSZ + 32) {                                           \
            int l = tid - MEMSZ;                                                 \
            float n0 = newmB[PP][l], n1 = newmB[PP][l + 32];                     \
            float nn = n0 * n0 + n1 * n1;                                        \
            _Pragma("unroll")                                                    \
            for (int o = 16; o; o >>= 1)                                         \
                nn += __shfl_xor_sync(0xffffffffu, nn, o);                       \
            if (l == 0) __stcg(&g_pnn[PP][b][s], nn);                            \
        }                                                                        \
    } while (0)

    PRE_PHASE(0);   // step-0 partials

    for (int step = 0; step < NSTEP; ++step) {
        const int p = step & 1;

        // ===== fixup: recompute changed column m* against updated memS ========
        if (step > 0) {
            int mstar = sChange;
            if (tid < CHUNK) {
                float acc = 0.0f;
                #pragma unroll 4
                for (int d = 0; d < DSLICE; ++d)
                    acc = fmaf(chunkS[d][tid], memS[d][mstar], acc);
                __stcg(&g_plog[p][b][s][tid][mstar], acc);
            } else if (tid == CHUNK) {
                float pd = 0.0f, pm = 0.0f;
                #pragma unroll 4
                for (int d = 0; d < DSLICE; ++d) {
                    float mv = memS[d][mstar];
                    pd = fmaf(newmB[p][d], mv, pd);
                    pm = fmaf(mv, mv, pm);
                }
                __stcg(&g_pdot[p][b][s][mstar], pd);
                __stcg(&g_pmm [p][b][s][mstar], pm);
            }
        }

        // per-batch barrier (proven): release, arrive, spin for 8 siblings
        __threadfence();
        __syncthreads();
        if (tid == 0) {
            atomicAdd(&g_cnt[step][b], 1u);
            const volatile unsigned* pc = &g_cnt[step][b];
            while (*pc < (unsigned)NSPLIT) { }
            __threadfence();
        }
        __syncthreads();

        // ===== consumer chain (all 256 threads; arithmetic exact) =============
        for (int q = tid; q < CHUNK * (MEMSZ / 4); q += NTHR) {
            int c  = q >> 4;
            int mq = q & 15;
            float4 r = make_float4(0, 0, 0, 0);
            #pragma unroll
            for (int ss = 0; ss < NSPLIT; ++ss) {
                float4 t4 = __ldcg((const float4*)&g_plog[p][b][ss][c][mq * 4]);
                r.x += t4.x; r.y += t4.y; r.z += t4.z; r.w += t4.w;
            }
            *(float4*)&logS[c][4 * mq] = r;
        }
        __syncthreads();
        for (int c = warp; c < CHUNK; c += (NTHR / 32)) {
            float w0 = logS[c][lane]      * scale;
            float w1 = logS[c][lane + 32] * scale;
            float mx = fmaxf(w0, w1);
            #pragma unroll
            for (int o = 16; o; o >>= 1) mx = fmaxf(mx, __shfl_xor_sync(0xffffffffu, mx, o));
            float e0 = __expf(w0 - mx), e1 = __expf(w1 - mx);
            float sm = e0 + e1;
            #pragma unroll
            for (int o = 16; o; o >>= 1) sm += __shfl_xor_sync(0xffffffffu, sm, o);
            float inv = 1.0f / sm;
            logS[c][lane]      = e0 * inv;
            logS[c][lane + 32] = e1 * inv;
        }
        __syncthreads();
        if (tid < MEMSZ) {
            float sc = 0.0f;
            #pragma unroll
            for (int c = 0; c < CHUNK; ++c) sc += logS[c][tid];   // exact serial
            score[tid] = sc * (1.0f / CHUNK);
        } else if (tid < 2 * MEMSZ) {
            int m = tid - MEMSZ;
            float pd = 0.0f, pm = 0.0f, nn = 0.0f;
            #pragma unroll
            for (int ss = 0; ss < NSPLIT; ++ss) {
                pd += __ldcg(&g_pdot[p][b][ss][m]);
                pm += __ldcg(&g_pmm [p][b][ss][m]);
                nn += __ldcg(&g_pnn [p][b][ss]);
            }
            simS[m] = pd / (sqrtf(nn + 1e-8f) * sqrtf(pm + 1e-8f));
        }
        __syncthreads();
        if (warp == 0) {
            float s0 = score[lane], s1 = score[lane + 32];
            float e = -(log2f(s0 + EPSF) * s0 + log2f(s1 + EPSF) * s1);
            #pragma unroll
            for (int o = 16; o; o >>= 1) e += __shfl_xor_sync(0xffffffffu, e, o);
            if (lane == 0 && s == 0) __stcg(&g_ent[step][b], e);
        } else if (warp == 1) {
            float r0 = (msS[lane]      + score[lane])      / (mfS[lane]      + 1.0f);
            float r1 = (msS[lane + 32] + score[lane + 32]) / (mfS[lane + 32] + 1.0f);
            float v; int idx;
            if (r1 < r0) { v = r1; idx = lane + 32; } else { v = r0; idx = lane; }
            #pragma unroll
            for (int o = 16; o; o >>= 1) {
                float ov = __shfl_xor_sync(0xffffffffu, v, o);
                int   oi = __shfl_xor_sync(0xffffffffu, idx, o);
                if (ov < v || (ov == v && oi < idx)) { v = ov; idx = oi; }
            }
            if (lane == 0) sRepl = idx;
        } else if (warp == 2) {
            float w0 = simS[lane], w1 = simS[lane + 32];
            float v; int idx;
            if (w1 > w0) { v = w1; idx = lane + 32; } else { v = w0; idx = lane; }
            #pragma unroll
            for (int o = 16; o; o >>= 1) {
                float ov = __shfl_xor_sync(0xffffffffu, v, o);
                int   oi = __shfl_xor_sync(0xffffffffu, idx, o);
                if (ov > v || (ov == v && oi < idx)) { v = ov; idx = oi; }
            }
            if (lane == 0) sMerge = idx;
        }
        __syncthreads();

        // ===== pre-work for step s+1 (hides the cross-batch entropy wait) =====
        if (step + 1 < NSTEP) {
            // install chunk s+1 (chunk s dead: fixup done)
            chunkS[q0_d * 4 + 0][q0_c] = v0.x; chunkS[q0_d * 4 + 1][q0_c] = v0.y;
            chunkS[q0_d * 4 + 2][q0_c] = v0.z; chunkS[q0_d * 4 + 3][q0_c] = v0.w;
            chunkS[q1_d * 4 + 0][q1_c] = v1.x; chunkS[q1_d * 4 + 1][q1_c] = v1.y;
            chunkS[q1_d * 4 + 2][q1_c] = v1.z; chunkS[q1_d * 4 + 3][q1_c] = v1.w;
            __syncthreads();
            // prefetch chunk s+2
            if (step + 2 < NSTEP) {
                const float* xb = x + ((size_t)b * TLEN + (size_t)(step + 2) * CHUNK) * DIM + d0;
                v0 = *(const float4*)(xb + (size_t)q0_c * DIM + q0_d * 4);
                v1 = *(const float4*)(xb + (size_t)q1_c * DIM + q1_d * 4);
            }
            // partials for step s+1 vs mem_s-minus-update (fixup corrects m*)
            PRE_PHASE(p ^ 1);
        }
        __syncthreads();

        // ===== cross-batch entropy: payload-as-flag spin (skew ~0 by now) =====
        if (tid < BATCH) {
            const volatile float* pe = &g_ent[step][tid];
            float v;
            do { v = *pe; } while (v == 0.0f);
            entS[tid] = v;
        }
        __syncthreads();

        // ===== P3: global branch + slice-local update ==========================
        float em = 0.0f;
        #pragma unroll
        for (int bb = 0; bb < BATCH; ++bb) em += entS[bb];   // exact serial
        em *= (1.0f / BATCH);

        if (em > thr) {
            int rm = sRepl;
            if (tid < DSLICE) {
                memS[tid][rm] = newmB[p][tid];
            } else if (tid < DSLICE + MEMSZ) {
                int m = tid - DSLICE;
                float sn = msS[m] + score[m];
                float fn = mfS[m] + 1.0f;
                if (m == rm) { sn = 0.0f; fn = 1.0f; }
                msS[m] = sn; mfS[m] = fn;
            }
        } else {
            int im = sMerge;
            if (tid < DSLICE) {
                float old = memS[tid][im];
                memS[tid][im] = old + (0.7f * newmB[p][tid] - 0.7f * old);
            }
        }
        if (tid == 0) sChange = (em > thr) ? sRepl : sMerge;
        __syncthreads();
    }

    // write final mem slice
    for (int i = tid; i < MEMSZ * DSLICE; i += NTHR) {
        int m = i >> 6;
        int d = i & 63;
        out[((size_t)b * MEMSZ + m) * DIM + d0 + d] = memS[d][m];
    }
}

extern "C" void kernel_launch(void* const* d_in, const int* in_sizes, int n_in,
                              void* d_out, int out_size) {
    const float* x        = (const float*)d_in[0];
    const float* mem_init = (const float*)d_in[1];
    if (n_in >= 2 && in_sizes[0] < in_sizes[1]) {
        const float* t = x; x = mem_init; mem_init = t;
    }
    float* out = (float*)d_out;

    zero_flags_kernel<<<4, 512>>>();
    memk<<<NBLK, NTHR>>>(x, mem_init, out);
}

// round 15
// speedup vs baseline: 1.2601x; 1.0975x over previous
#include <cuda_runtime.h>
#include <cstdint>

#define BATCH  16
#define TLEN   4096
#define DIM    512
#define CHUNK  32
#define MEMSZ  64
#define NSPLIT 8
#define DSLICE (DIM / NSPLIT)     // 64
#define NSTEP  (TLEN / CHUNK)     // 128
#define NBLK   (BATCH * NSPLIT)   // 128 blocks = 16 clusters of 8
#define NTHR   256
#define EPSF   1e-10f

// ---- cross-block scratch (parity double-buffered) ----
__device__ float g_plog[2][BATCH][NSPLIT][CHUNK][MEMSZ];
__device__ float g_pdot[2][BATCH][NSPLIT][MEMSZ];
__device__ float g_pmm [2][BATCH][NSPLIT][MEMSZ];
__device__ float g_pnn [2][BATCH][NSPLIT];
__device__ float g_ent [NSTEP][BATCH];    // entropy: payload == ready flag (never 0.0)

__global__ void zero_flags_kernel() {
    int t = blockIdx.x * blockDim.x + threadIdx.x;
    if (t < NSTEP * BATCH) ((float*)g_ent)[t] = 0.0f;
}

__device__ __forceinline__ uint32_t smem_u32(const void* p) {
    uint32_t a;
    asm("{ .reg .u64 t; cvta.to.shared.u64 t, %1; cvt.u32.u64 %0, t; }" : "=r"(a) : "l"(p));
    return a;
}
__device__ __forceinline__ void cluster_sync_() {
    asm volatile("barrier.cluster.arrive.aligned;" ::: "memory");
    asm volatile("barrier.cluster.wait.aligned;"   ::: "memory");
}
__device__ __forceinline__ void st_cluster_f32(uint32_t laddr, int rank, float v) {
    uint32_t r;
    asm volatile("mapa.shared::cluster.u32 %0, %1, %2;" : "=r"(r) : "r"(laddr), "r"(rank));
    asm volatile("st.shared::cluster.f32 [%0], %1;" :: "r"(r), "f"(v) : "memory");
}

__global__ void __launch_bounds__(NTHR, 1) __cluster_dims__(NSPLIT, 1, 1)
memk(const float* __restrict__ x, const float* __restrict__ mem_init,
     float* __restrict__ out)
{
    __shared__ float memS  [DSLICE][MEMSZ + 4]; // [d][m], pitch 68
    __shared__ float chunkS[DSLICE][CHUNK + 2]; // [d][c], pitch 34
    __shared__ float logS  [CHUNK][MEMSZ];      // probs (assembled via DSMEM)
    __shared__ float newmB [2][DSLICE];
    __shared__ float score [MEMSZ];
    __shared__ float msS   [MEMSZ];
    __shared__ float mfS   [MEMSZ];
    __shared__ float simS  [MEMSZ];
    __shared__ float entS  [BATCH];
    __shared__ int   sRepl, sMerge, sChange;

    const int tid  = threadIdx.x;
    const int bid  = blockIdx.x;
    const int b    = bid >> 3;
    const int s    = bid & 7;
    const int d0   = s * DSLICE;
    const int lane = tid & 31;
    const int warp = tid >> 5;

    for (int i = tid; i < DSLICE * MEMSZ; i += NTHR) {
        int m = i >> 6;
        int d = i & 63;
        memS[d][m] = mem_init[((size_t)b * MEMSZ + m) * DIM + d0 + d];
    }
    for (int i = tid; i < MEMSZ; i += NTHR) { msS[i] = 0.0f; mfS[i] = 0.0f; }

    const float scale = 1.0f / sqrtf((float)DIM);
    const float thr   = 0.5f * log2f((float)MEMSZ + EPSF);  // = 3.0

    // GEMM 2c x 4m tile on all 256 threads (proven layout/bits)
    const int i_c = tid >> 4;
    const int j_m = tid & 15;

    const int q0_c = tid >> 4,         q0_d = tid & 15;
    const int q1_c = (tid + 256) >> 4, q1_d = tid & 15;

    float4 v0, v1;
    {
        const float* xb = x + ((size_t)b * TLEN) * DIM + d0;
        v0 = *(const float4*)(xb + (size_t)q0_c * DIM + q0_d * 4);
        v1 = *(const float4*)(xb + (size_t)q1_c * DIM + q1_d * 4);
    }
    __syncthreads();   // memS init complete
    chunkS[q0_d * 4 + 0][q0_c] = v0.x; chunkS[q0_d * 4 + 1][q0_c] = v0.y;
    chunkS[q0_d * 4 + 2][q0_c] = v0.z; chunkS[q0_d * 4 + 3][q0_c] = v0.w;
    chunkS[q1_d * 4 + 0][q1_c] = v1.x; chunkS[q1_d * 4 + 1][q1_c] = v1.y;
    chunkS[q1_d * 4 + 2][q1_c] = v1.z; chunkS[q1_d * 4 + 3][q1_c] = v1.w;
    __syncthreads();
    {
        const float* xb = x + ((size_t)b * TLEN + (size_t)CHUNK) * DIM + d0;
        v0 = *(const float4*)(xb + (size_t)q0_c * DIM + q0_d * 4);
        v1 = *(const float4*)(xb + (size_t)q1_c * DIM + q1_d * 4);
    }

    // ---- pre-phase (R9/R13 phase-1 verbatim; bit-identical chains) ----
    #define PRE_PHASE(PP)                                                        \
    do {                                                                         \
        float a00=0,a01=0,a02=0,a03=0, a10=0,a11=0,a12=0,a13=0;                  \
        _Pragma("unroll 4")                                                      \
        for (int d = 0; d < DSLICE; ++d) {                                       \
            float2 av = *(const float2*)&chunkS[d][2 * i_c];                     \
            float4 bv = *(const float4*)&memS[d][4 * j_m];                       \
            a00 = fmaf(av.x, bv.x, a00); a01 = fmaf(av.x, bv.y, a01);            \
            a02 = fmaf(av.x, bv.z, a02); a03 = fmaf(av.x, bv.w, a03);            \
            a10 = fmaf(av.y, bv.x, a10); a11 = fmaf(av.y, bv.y, a11);            \
            a12 = fmaf(av.y, bv.z, a12); a13 = fmaf(av.y, bv.w, a13);            \
        }                                                                        \
        __stcg((float4*)&g_plog[PP][b][s][2 * i_c][4 * j_m],                     \
               make_float4(a00, a01, a02, a03));                                 \
        __stcg((float4*)&g_plog[PP][b][s][2 * i_c + 1][4 * j_m],                 \
               make_float4(a10, a11, a12, a13));                                 \
        if (tid < DSLICE) {                                                      \
            float mx = chunkS[tid][0];                                           \
            _Pragma("unroll")                                                    \
            for (int c = 1; c < CHUNK; ++c) mx = fmaxf(mx, chunkS[tid][c]);      \
            newmB[PP][tid] = mx;                                                 \
        }                                                                        \
        __syncthreads();                                                         \
        if (tid < MEMSZ) {                                                       \
            float pd = 0.0f, pm = 0.0f;                                          \
            _Pragma("unroll 4")                                                  \
            for (int d = 0; d < DSLICE; ++d) {                                   \
                float mv = memS[d][tid];                                         \
                pd = fmaf(newmB[PP][d], mv, pd);                                 \
                pm = fmaf(mv, mv, pm);                                           \
            }                                                                    \
            __stcg(&g_pdot[PP][b][s][tid], pd);                                  \
            __stcg(&g_pmm [PP][b][s][tid], pm);                                  \
        } else if (tid < MEMSZ + 32) {                                           \
            int l = tid - MEMSZ;                                                 \
            float n0 = newmB[PP][l], n1 = newmB[PP][l + 32];                     \
            float nn = n0 * n0 + n1 * n1;                                        \
            _Pragma("unroll")                                                    \
            for (int o = 16; o; o >>= 1)                                         \
                nn += __shfl_xor_sync(0xffffffffu, nn, o);                       \
            if (l == 0) __stcg(&g_pnn[PP][b][s], nn);                            \
        }                                                                        \
    } while (0)

    PRE_PHASE(0);

    for (int step = 0; step < NSTEP; ++step) {
        const int p = step & 1;

        // ===== fixup: changed column m* vs updated memS (reads chunk s) =======
        if (step > 0) {
            int mstar = sChange;
            if (tid < CHUNK) {
                float acc = 0.0f;
                #pragma unroll 4
                for (int d = 0; d < DSLICE; ++d)
                    acc = fmaf(chunkS[d][tid], memS[d][mstar], acc);
                __stcg(&g_plog[p][b][s][tid][mstar], acc);
            } else if (tid == CHUNK) {
                float pd = 0.0f, pm = 0.0f;
                #pragma unroll 4
                for (int d = 0; d < DSLICE; ++d) {
                    float mv = memS[d][mstar];
                    pd = fmaf(newmB[p][d], mv, pd);
                    pm = fmaf(mv, mv, pm);
                }
                __stcg(&g_pdot[p][b][s][mstar], pd);
                __stcg(&g_pmm [p][b][s][mstar], pm);
            }
        }

        cluster_sync_();   // sync1: all sibling partials (pre-phase + fixup) visible

        // install chunk s+1 (chunk s dead after fixup), then prefetch s+2
        if (step + 1 < NSTEP) {
            chunkS[q0_d * 4 + 0][q0_c] = v0.x; chunkS[q0_d * 4 + 1][q0_c] = v0.y;
            chunkS[q0_d * 4 + 2][q0_c] = v0.z; chunkS[q0_d * 4 + 3][q0_c] = v0.w;
            chunkS[q1_d * 4 + 0][q1_c] = v1.x; chunkS[q1_d * 4 + 1][q1_c] = v1.y;
            chunkS[q1_d * 4 + 2][q1_c] = v1.z; chunkS[q1_d * 4 + 3][q1_c] = v1.w;
        }
        if (step + 2 < NSTEP) {
            const float* xb = x + ((size_t)b * TLEN + (size_t)(step + 2) * CHUNK) * DIM + d0;
            v0 = *(const float4*)(xb + (size_t)q0_c * DIM + q0_d * 4);
            v1 = *(const float4*)(xb + (size_t)q1_c * DIM + q1_d * 4);
        }

        if (warp < 4) {
            // ===== own row: reduce (exact ss order) + softmax (exact tree) ====
            int c = 4 * s + warp;
            float vv0 = 0.0f, vv1 = 0.0f;
            #pragma unroll
            for (int ss = 0; ss < NSPLIT; ++ss) {
                vv0 += __ldcg(&g_plog[p][b][ss][c][lane]);
                vv1 += __ldcg(&g_plog[p][b][ss][c][lane + 32]);
            }
            float w0 = vv0 * scale;
            float w1 = vv1 * scale;
            float mx = fmaxf(w0, w1);
            #pragma unroll
            for (int o = 16; o; o >>= 1) mx = fmaxf(mx, __shfl_xor_sync(0xffffffffu, mx, o));
            float e0 = __expf(w0 - mx), e1 = __expf(w1 - mx);
            float sm = e0 + e1;
            #pragma unroll
            for (int o = 16; o; o >>= 1) sm += __shfl_xor_sync(0xffffffffu, sm, o);
            float inv = 1.0f / sm;
            float p0 = e0 * inv, p1 = e1 * inv;
            // broadcast probs to all 8 cluster CTAs' logS (incl. self)
            uint32_t a0 = smem_u32(&logS[c][lane]);
            uint32_t a1 = smem_u32(&logS[c][lane + 32]);
            #pragma unroll
            for (int r = 0; r < NSPLIT; ++r) {
                st_cluster_f32(a0, r, p0);
                st_cluster_f32(a1, r, p1);
            }
        } else {
            // ===== sim reduce (exact ss order) on warps 4-5 ====================
            int t = tid - 128;
            if (t < MEMSZ) {
                float pd = 0.0f, pm = 0.0f, nn = 0.0f;
                #pragma unroll
                for (int ss = 0; ss < NSPLIT; ++ss) {
                    pd += __ldcg(&g_pdot[p][b][ss][t]);
                    pm += __ldcg(&g_pmm [p][b][ss][t]);
                    nn += __ldcg(&g_pnn [p][b][ss]);
                }
                simS[t] = pd / (sqrtf(nn + 1e-8f) * sqrtf(pm + 1e-8f));
            }
        }

        cluster_sync_();   // sync2: probs assembled everywhere; chunkS installed

        // ===== score: exact serial c=0..31 over assembled probs ===============
        if (tid < MEMSZ) {
            float sc = 0.0f;
            #pragma unroll
            for (int c = 0; c < CHUNK; ++c) sc += logS[c][tid];
            score[tid] = sc * (1.0f / CHUNK);
        }
        __syncthreads();
        if (warp == 0) {
            float s0 = score[lane], s1 = score[lane + 32];
            float e = -(log2f(s0 + EPSF) * s0 + log2f(s1 + EPSF) * s1);
            #pragma unroll
            for (int o = 16; o; o >>= 1) e += __shfl_xor_sync(0xffffffffu, e, o);
            if (lane == 0 && s == 0) __stcg(&g_ent[step][b], e);
        } else if (warp == 1) {
            float r0 = (msS[lane]      + score[lane])      / (mfS[lane]      + 1.0f);
            float r1 = (msS[lane + 32] + score[lane + 32]) / (mfS[lane + 32] + 1.0f);
            float v; int idx;
            if (r1 < r0) { v = r1; idx = lane + 32; } else { v = r0; idx = lane; }
            #pragma unroll
            for (int o = 16; o; o >>= 1) {
                float ov = __shfl_xor_sync(0xffffffffu, v, o);
                int   oi = __shfl_xor_sync(0xffffffffu, idx, o);
                if (ov < v || (ov == v && oi < idx)) { v = ov; idx = oi; }
            }
            if (lane == 0) sRepl = idx;
        } else if (warp == 2) {
            float w0 = simS[lane], w1 = simS[lane + 32];
            float v; int idx;
            if (w1 > w0) { v = w1; idx = lane + 32; } else { v = w0; idx = lane; }
            #pragma unroll
            for (int o = 16; o; o >>= 1) {
                float ov = __shfl_xor_sync(0xffffffffu, v, o);
                int   oi = __shfl_xor_sync(0xffffffffu, idx, o);
                if (ov > v || (ov == v && oi < idx)) { v = ov; idx = oi; }
            }
            if (lane == 0) sMerge = idx;
        }

        // ===== pre-work for step s+1 (hides cross-batch entropy skew) =========
        if (step + 1 < NSTEP) {
            PRE_PHASE(p ^ 1);      // contains an internal __syncthreads
        } else {
            __syncthreads();       // order argsel writes before P3
        }

        // ===== cross-batch entropy: payload-as-flag spin (proven) =============
        if (tid < BATCH) {
            const volatile float* pe = &g_ent[step][tid];
            float v;
            do { v = *pe; } while (v == 0.0f);
            entS[tid] = v;
        }
        __syncthreads();

        // ===== P3: global branch + slice-local update ==========================
        float em = 0.0f;
        #pragma unroll
        for (int bb = 0; bb < BATCH; ++bb) em += entS[bb];   // exact serial
        em *= (1.0f / BATCH);

        if (em > thr) {
            int rm = sRepl;
            if (tid < DSLICE) {
                memS[tid][rm] = newmB[p][tid];
            } else if (tid < DSLICE + MEMSZ) {
                int m = tid - DSLICE;
                float sn = msS[m] + score[m];
                float fn = mfS[m] + 1.0f;
                if (m == rm) { sn = 0.0f; fn = 1.0f; }
                msS[m] = sn; mfS[m] = fn;
            }
        } else {
            int im = sMerge;
            if (tid < DSLICE) {
                float old = memS[tid][im];
                memS[tid][im] = old + (0.7f * newmB[p][tid] - 0.7f * old);
            }
        }
        if (tid == 0) sChange = (em > thr) ? sRepl : sMerge;
        __syncthreads();
    }

    // write final mem slice
    for (int i = tid; i < MEMSZ * DSLICE; i += NTHR) {
        int m = i >> 6;
        int d = i & 63;
        out[((size_t)b * MEMSZ + m) * DIM + d0 + d] = memS[d][m];
    }
}

extern "C" void kernel_launch(void* const* d_in, const int* in_sizes, int n_in,
                              void* d_out, int out_size) {
    const float* x        = (const float*)d_in[0];
    const float* mem_init = (const float*)d_in[1];
    if (n_in >= 2 && in_sizes[0] < in_sizes[1]) {
        const float* t = x; x = mem_init; mem_init = t;
    }
    float* out = (float*)d_out;

    zero_flags_kernel<<<4, 512>>>();
    memk<<<NBLK, NTHR>>>(x, mem_init, out);
}